// round 8
// baseline (speedup 1.0000x reference)
#include <cuda_runtime.h>
#include <cuda_fp16.h>
#include <math.h>
#include <stdint.h>

// Problem constants
#define BATCH 8192
#define SEQ   4
#define CDIM  1024
#define HEADS 16
#define HDIM  64
#define PDIM  4
#define MROWS (BATCH * SEQ)        // 32768
#define QKVC  (3 * CDIM)           // 3072
#define OUT_ELEMS ((size_t)MROWS * CDIM)
#define SEL_ELEMS ((size_t)BATCH * HEADS * HEADS)

// -------- global scratch (allocation-free per harness rules) --------
__device__ __half g_xh [(size_t)MROWS * CDIM];   // x in fp16
__device__ __half g_wqh[(size_t)QKVC * CDIM];    // W_qkv^T fp16 [3072,1024]
__device__ __half g_wph[(size_t)CDIM * CDIM];    // W_proj fp16 [1024,1024]
__device__ float  g_qkv[(size_t)MROWS * QKVC];   // qkv f32
__device__ __half g_hoh[(size_t)MROWS * CDIM];   // attention out fp16

// ======================= helpers =======================
__device__ __forceinline__ uint32_t smem_u32(const void* p) {
    return (uint32_t)__cvta_generic_to_shared(p);
}
__device__ __forceinline__ void cp16(uint32_t dst, const void* src) {
    asm volatile("cp.async.cg.shared.global [%0], [%1], 16;" :: "r"(dst), "l"(src));
}
#define CP_COMMIT()  asm volatile("cp.async.commit_group;" ::: "memory")
#define CP_WAIT1()   asm volatile("cp.async.wait_group 1;" ::: "memory")

#define LDSM4(r, a) \
    asm volatile("ldmatrix.sync.aligned.m8n8.x4.shared.b16 {%0,%1,%2,%3}, [%4];" \
        : "=r"((r)[0]), "=r"((r)[1]), "=r"((r)[2]), "=r"((r)[3]) : "r"(a))

#define MMA16816(d, a, b0, b1) \
    asm volatile("mma.sync.aligned.m16n8k16.row.col.f32.f16.f16.f32 " \
        "{%0,%1,%2,%3}, {%4,%5,%6,%7}, {%8,%9}, {%0,%1,%2,%3};" \
        : "+f"((d)[0]), "+f"((d)[1]), "+f"((d)[2]), "+f"((d)[3]) \
        : "r"((a)[0]), "r"((a)[1]), "r"((a)[2]), "r"((a)[3]), "r"(b0), "r"(b1))

// ======================= HMMA fp16 GEMM =======================
// C[M,N] = A[M,K] * B[N,K]^T, A/B fp16 K-major, C f32. K % 32 == 0, N % 256 == 0.
// CTA 128x256, BK=32, 3 stages, 256 threads; 8 warps in 2(m) x 4(n), 64x64 warp tile.
#define STAGE_BYTES 24576   // A 8KB + B 16KB
#define NSTAGE 3
#define G_SMEM (NSTAGE * STAGE_BYTES)   // 73728

template<bool BIAS>
__global__ void __launch_bounds__(256) gemm_hmma(
    const __half* __restrict__ A, const __half* __restrict__ B,
    const float* __restrict__ bias, float* __restrict__ C,
    int Mn, int Nn, int Kn)
{
    extern __shared__ __align__(128) char smem[];
    const uint32_t sb = smem_u32(smem);
    const int tid = threadIdx.x;
    const int lane = tid & 31, wid = tid >> 5;
    const int warp_m = wid & 1, warp_n = wid >> 1;     // 2 x 4 warp grid
    const int m0 = blockIdx.y * 128, n0 = blockIdx.x * 256;
    const int KT = Kn >> 5;

    const __half* Ag = A + (size_t)m0 * Kn;
    const __half* Bg = B + (size_t)n0 * Kn;

    // load coords: A = 512 chunks (2/thread), B = 1024 chunks (4/thread)
    // chunk id -> row = id>>2, c = id&3 ; swizzle c ^= (row>>1)&3, 64B rows
    int a_row[2], a_c[2]; uint32_t a_sw[2];
    int b_row[4], b_c[4]; uint32_t b_sw[4];
    #pragma unroll
    for (int h = 0; h < 2; h++) {
        int id = tid + h * 256;
        a_row[h] = id >> 2; a_c[h] = id & 3;
        a_sw[h] = (uint32_t)(a_row[h] * 64 + ((a_c[h] ^ ((a_row[h] >> 1) & 3)) << 4));
    }
    #pragma unroll
    for (int h = 0; h < 4; h++) {
        int id = tid + h * 256;
        b_row[h] = id >> 2; b_c[h] = id & 3;
        b_sw[h] = (uint32_t)(b_row[h] * 64 + ((b_c[h] ^ ((b_row[h] >> 1) & 3)) << 4));
    }

    #define LD_STAGE(s, kt) do { \
        uint32_t abase_ = sb + (s) * STAGE_BYTES; \
        uint32_t bbase_ = abase_ + 8192; \
        _Pragma("unroll") \
        for (int h = 0; h < 2; h++) \
            cp16(abase_ + a_sw[h], Ag + (size_t)a_row[h] * Kn + (kt) * 32 + a_c[h] * 8); \
        _Pragma("unroll") \
        for (int h = 0; h < 4; h++) \
            cp16(bbase_ + b_sw[h], Bg + (size_t)b_row[h] * Kn + (kt) * 32 + b_c[h] * 8); \
    } while (0)

    LD_STAGE(0, 0); CP_COMMIT();
    LD_STAGE(1, 1); CP_COMMIT();

    float acc[4][8][4];
    #pragma unroll
    for (int i = 0; i < 4; i++)
        #pragma unroll
        for (int j = 0; j < 8; j++)
            #pragma unroll
            for (int q = 0; q < 4; q++) acc[i][j][q] = 0.0f;

    const int a_row_l = lane & 15;
    const int a_csel  = lane >> 4;
    const int b_row_l = ((lane >> 4) << 3) + (lane & 7);
    const int b_csel  = (lane >> 3) & 1;

    int stage = 0;
    for (int kt = 0; kt < KT; kt++) {
        CP_WAIT1();
        __syncthreads();
        if (kt + 2 < KT) {
            int s2 = stage + 2; if (s2 >= NSTAGE) s2 -= NSTAGE;
            LD_STAGE(s2, kt + 2);
        }
        CP_COMMIT();

        const uint32_t abase = sb + stage * STAGE_BYTES;
        const uint32_t bbase = abase + 8192;

        #pragma unroll
        for (int k16 = 0; k16 < 2; k16++) {
            uint32_t ar[4][4], br[4][4];
            #pragma unroll
            for (int i = 0; i < 4; i++) {
                int row = warp_m * 64 + i * 16 + a_row_l;
                int c = k16 * 2 + a_csel;
                LDSM4(ar[i], abase + row * 64 + ((c ^ ((row >> 1) & 3)) << 4));
            }
            #pragma unroll
            for (int j = 0; j < 4; j++) {
                int row = warp_n * 64 + j * 16 + b_row_l;
                int c = k16 * 2 + b_csel;
                LDSM4(br[j], bbase + row * 64 + ((c ^ ((row >> 1) & 3)) << 4));
            }
            #pragma unroll
            for (int i = 0; i < 4; i++)
                #pragma unroll
                for (int j = 0; j < 8; j++)
                    MMA16816(acc[i][j], ar[i], br[j >> 1][(j & 1) * 2],
                             br[j >> 1][(j & 1) * 2 + 1]);
        }
        if (++stage == NSTAGE) stage = 0;
    }

    // epilogue
    #pragma unroll
    for (int i = 0; i < 4; i++) {
        const int r0 = m0 + warp_m * 64 + i * 16 + (lane >> 2);
        #pragma unroll
        for (int j = 0; j < 8; j++) {
            const int col = n0 + warp_n * 64 + j * 8 + (lane & 3) * 2;
            float2 v0 = make_float2(acc[i][j][0], acc[i][j][1]);
            float2 v1 = make_float2(acc[i][j][2], acc[i][j][3]);
            if (BIAS) {
                float b0v = bias[col], b1v = bias[col + 1];
                v0.x += b0v; v0.y += b1v; v1.x += b0v; v1.y += b1v;
            }
            *reinterpret_cast<float2*>(&C[(size_t)r0 * Nn + col]) = v0;
            *reinterpret_cast<float2*>(&C[(size_t)(r0 + 8) * Nn + col]) = v1;
        }
    }
}

// ======================= conversion kernels =======================
__global__ void f2h_k(const float4* __restrict__ in, __half2* __restrict__ out, int n4) {
    int i = blockIdx.x * blockDim.x + threadIdx.x;
    if (i < n4) {
        float4 v = in[i];
        out[2 * i]     = __floats2half2_rn(v.x, v.y);
        out[2 * i + 1] = __floats2half2_rn(v.z, v.w);
    }
}

// in [R, Cc] f32 row-major -> out [Cc, R] fp16 row-major
__global__ void transpose_h_k(const float* __restrict__ in, __half* __restrict__ out,
                              int R, int Cc) {
    __shared__ float t[32][33];
    const int bx = blockIdx.x * 32;
    const int by = blockIdx.y * 32;
    const int tx = threadIdx.x, ty = threadIdx.y;
#pragma unroll
    for (int j = 0; j < 32; j += 8)
        t[ty + j][tx] = in[(size_t)(by + ty + j) * Cc + bx + tx];
    __syncthreads();
#pragma unroll
    for (int j = 0; j < 32; j += 8)
        out[(size_t)(bx + ty + j) * R + by + tx] = __float2half_rn(t[tx][ty + j]);
}

// ======================= per-batch attention kernel =======================
__global__ void __launch_bounds__(512) attn_kernel(
    const float* __restrict__ qkv,
    const float* __restrict__ W_E, const float* __restrict__ W_F,
    __half* __restrict__ ho, float* __restrict__ sel_out)
{
    __shared__ float s[SEQ * QKVC];  // 48 KB
    const int b = blockIdx.x;
    const int tid = threadIdx.x;

    const float4* src = reinterpret_cast<const float4*>(qkv + (size_t)b * SEQ * QKVC);
    float4* dst = reinterpret_cast<float4*>(s);
#pragma unroll
    for (int i = 0; i < 6; i++) dst[tid + i * 512] = src[tid + i * 512];
    __syncthreads();

    const int h = tid >> 5, lane = tid & 31;
    const int d0 = lane << 1;

    float q[SEQ][2], kk[SEQ][2], vv[SEQ][2];
#pragma unroll
    for (int n = 0; n < SEQ; n++) {
#pragma unroll
        for (int j = 0; j < 2; j++) {
            q[n][j]  = s[n * QKVC +            h * HDIM + d0 + j] * 0.125f;
            kk[n][j] = s[n * QKVC + CDIM +     h * HDIM + d0 + j];
            vv[n][j] = s[n * QKVC + 2 * CDIM + h * HDIM + d0 + j];
        }
    }

    float wE[16], wF[16];
#pragma unroll
    for (int i = 0; i < 16; i++) { wE[i] = __ldg(&W_E[i]); wF[i] = __ldg(&W_F[i]); }

    float klow[PDIM][2], vlow[PDIM][2];
#pragma unroll
    for (int p = 0; p < PDIM; p++)
#pragma unroll
        for (int j = 0; j < 2; j++) {
            klow[p][j] = wE[p*4+0]*kk[0][j] + wE[p*4+1]*kk[1][j]
                       + wE[p*4+2]*kk[2][j] + wE[p*4+3]*kk[3][j];
            vlow[p][j] = wF[p*4+0]*vv[0][j] + wF[p*4+1]*vv[1][j]
                       + wF[p*4+2]*vv[2][j] + wF[p*4+3]*vv[3][j];
        }

    float attn[SEQ][PDIM];
#pragma unroll
    for (int n = 0; n < SEQ; n++)
#pragma unroll
        for (int p = 0; p < PDIM; p++) {
            float part = q[n][0]*klow[p][0] + q[n][1]*klow[p][1];
#pragma unroll
            for (int o = 16; o > 0; o >>= 1)
                part += __shfl_xor_sync(0xffffffffu, part, o);
            attn[n][p] = part;
        }

#pragma unroll
    for (int n = 0; n < SEQ; n++) {
        float mx = fmaxf(fmaxf(attn[n][0], attn[n][1]), fmaxf(attn[n][2], attn[n][3]));
        float e0 = expf(attn[n][0]-mx), e1 = expf(attn[n][1]-mx);
        float e2 = expf(attn[n][2]-mx), e3 = expf(attn[n][3]-mx);
        float inv = 1.0f / (e0 + e1 + e2 + e3);
        attn[n][0] = e0*inv; attn[n][1] = e1*inv; attn[n][2] = e2*inv; attn[n][3] = e3*inv;
    }

#pragma unroll
    for (int n = 0; n < SEQ; n++) {
        float o0 = attn[n][0]*vlow[0][0] + attn[n][1]*vlow[1][0]
                 + attn[n][2]*vlow[2][0] + attn[n][3]*vlow[3][0];
        float o1 = attn[n][0]*vlow[0][1] + attn[n][1]*vlow[1][1]
                 + attn[n][2]*vlow[2][1] + attn[n][3]*vlow[3][1];
        *reinterpret_cast<__half2*>(
            &ho[(size_t)(b * SEQ + n) * CDIM + h * HDIM + d0]) =
            __floats2half2_rn(o0, o1);
    }

    float selval = 0.0f;
#pragma unroll
    for (int g = 0; g < HEADS; g++) {
        float part = q[1][0] * s[2*QKVC + CDIM + g*HDIM + d0]
                   + q[1][1] * s[2*QKVC + CDIM + g*HDIM + d0 + 1];
#pragma unroll
        for (int o = 16; o > 0; o >>= 1)
            part += __shfl_xor_sync(0xffffffffu, part, o);
        if (lane == g) selval = part;
    }
    if (lane < HEADS)
        sel_out[(size_t)b * HEADS * HEADS + h * HEADS + lane] =
            1.0f / (1.0f + expf(-selval));
}

// ======================= launch =======================
extern "C" void kernel_launch(void* const* d_in, const int* in_sizes, int n_in,
                              void* d_out, int out_size) {
    const float* x      = (const float*)d_in[0];
    const float* W_qkv  = (const float*)d_in[1];
    const float* W_proj = (const float*)d_in[2];
    const float* b_proj = (const float*)d_in[3];
    const float* W_E    = (const float*)d_in[4];
    const float* W_F    = (const float*)d_in[5];
    float* out = (float*)d_out;
    float* sel = out + OUT_ELEMS;

    static __half *xh = nullptr, *wqh = nullptr, *wph = nullptr, *hoh = nullptr;
    static float *qkv = nullptr;
    if (!xh) {
        cudaGetSymbolAddress((void**)&xh,  g_xh);
        cudaGetSymbolAddress((void**)&wqh, g_wqh);
        cudaGetSymbolAddress((void**)&wph, g_wph);
        cudaGetSymbolAddress((void**)&hoh, g_hoh);
        cudaGetSymbolAddress((void**)&qkv, g_qkv);
        cudaFuncSetAttribute(gemm_hmma<false>,
            cudaFuncAttributeMaxDynamicSharedMemorySize, G_SMEM);
        cudaFuncSetAttribute(gemm_hmma<true>,
            cudaFuncAttributeMaxDynamicSharedMemorySize, G_SMEM);
    }

    // conversions
    f2h_k<<<(OUT_ELEMS / 4 + 255) / 256, 256>>>(
        (const float4*)x, (__half2*)xh, (int)(OUT_ELEMS / 4));
    transpose_h_k<<<dim3(QKVC / 32, CDIM / 32), dim3(32, 8)>>>(
        W_qkv, wqh, CDIM, QKVC);
    f2h_k<<<(CDIM * CDIM / 4 + 255) / 256, 256>>>(
        (const float4*)W_proj, (__half2*)wph, CDIM * CDIM / 4);

    // 1) qkv = x @ W_qkv
    gemm_hmma<false><<<dim3(QKVC / 256, MROWS / 128), 256, G_SMEM>>>(
        xh, wqh, nullptr, qkv, MROWS, QKVC, CDIM);
    // 2) attention middle + sel gate (fp32 math, fp16 output for GEMM2)
    attn_kernel<<<BATCH, 512>>>(qkv, W_E, W_F, hoh, sel);
    // 3) out = ho @ W_proj^T + b_proj
    gemm_hmma<true><<<dim3(CDIM / 256, MROWS / 128), 256, G_SMEM>>>(
        hoh, wph, b_proj, out, MROWS, CDIM, CDIM);
}

// round 12
// speedup vs baseline: 1.2514x; 1.2514x over previous
#include <cuda_runtime.h>
#include <cuda_fp16.h>
#include <math.h>
#include <stdint.h>

// Problem constants
#define BATCH 8192
#define SEQ   4
#define CDIM  1024
#define HEADS 16
#define HDIM  64
#define PDIM  4
#define MROWS (BATCH * SEQ)        // 32768
#define QKVC  (3 * CDIM)           // 3072
#define OUT_ELEMS ((size_t)MROWS * CDIM)
#define SEL_ELEMS ((size_t)BATCH * HEADS * HEADS)

// -------- global scratch (allocation-free per harness rules) --------
__device__ __half g_xh [(size_t)MROWS * CDIM];   // x in fp16
__device__ __half g_wqh[(size_t)QKVC * CDIM];    // W_qkv^T fp16 [3072,1024]
__device__ __half g_wph[(size_t)CDIM * CDIM];    // W_proj fp16 [1024,1024]
__device__ float  g_qkv[(size_t)MROWS * QKVC];   // qkv f32
__device__ __half g_hoh[(size_t)MROWS * CDIM];   // attention out fp16

// ======================= helpers =======================
__device__ __forceinline__ uint32_t smem_u32(const void* p) {
    return (uint32_t)__cvta_generic_to_shared(p);
}
__device__ __forceinline__ void cp16(uint32_t dst, const void* src) {
    asm volatile("cp.async.cg.shared.global [%0], [%1], 16;" :: "r"(dst), "l"(src));
}
#define CP_COMMIT()  asm volatile("cp.async.commit_group;" ::: "memory")
#define CP_WAIT2()   asm volatile("cp.async.wait_group 2;" ::: "memory")

#define LDSM4(r, a) \
    asm volatile("ldmatrix.sync.aligned.m8n8.x4.shared.b16 {%0,%1,%2,%3}, [%4];" \
        : "=r"((r)[0]), "=r"((r)[1]), "=r"((r)[2]), "=r"((r)[3]) : "r"(a))

#define MMA16816(d, a, b0, b1) \
    asm volatile("mma.sync.aligned.m16n8k16.row.col.f32.f16.f16.f32 " \
        "{%0,%1,%2,%3}, {%4,%5,%6,%7}, {%8,%9}, {%0,%1,%2,%3};" \
        : "+f"((d)[0]), "+f"((d)[1]), "+f"((d)[2]), "+f"((d)[3]) \
        : "r"((a)[0]), "r"((a)[1]), "r"((a)[2]), "r"((a)[3]), "r"(b0), "r"(b1))

// ======================= HMMA fp16 GEMM =======================
// C[M,N] = A[M,K] * B[N,K]^T, A/B fp16 K-major, C f32. K % 32 == 0, N % 128 == 0.
// CTA 128x128, BK=32, 4 stages, 128 threads; 4 warps in 2(m) x 2(n), 64x64 warp tile.
// __launch_bounds__(128, 2) -> 2 CTAs/SM guaranteed (256-reg budget/thread).
#define STAGE_BYTES 16384   // A 8KB + B 8KB
#define NSTAGE 4
#define G_SMEM (NSTAGE * STAGE_BYTES)   // 65536

template<bool BIAS>
__global__ void __launch_bounds__(128, 2) gemm_hmma(
    const __half* __restrict__ A, const __half* __restrict__ B,
    const float* __restrict__ bias, float* __restrict__ C,
    int Mn, int Nn, int Kn)
{
    extern __shared__ __align__(128) char smem[];
    const uint32_t sb = smem_u32(smem);
    const int tid = threadIdx.x;
    const int lane = tid & 31, wid = tid >> 5;
    const int warp_m = wid & 1, warp_n = wid >> 1;     // 2 x 2 warp grid
    const int m0 = blockIdx.y * 128, n0 = blockIdx.x * 128;
    const int KT = Kn >> 5;

    const __half* Ag = A + (size_t)m0 * Kn;
    const __half* Bg = B + (size_t)n0 * Kn;

    // load coords: A = 512 chunks (4/thread), B = 512 chunks (4/thread)
    // chunk id -> row = id>>2, c = id&3 ; swizzle c ^= (row>>1)&3, 64B rows
    int l_row[4], l_c[4]; uint32_t l_sw[4];
    #pragma unroll
    for (int h = 0; h < 4; h++) {
        int id = tid + h * 128;
        l_row[h] = id >> 2; l_c[h] = id & 3;
        l_sw[h] = (uint32_t)(l_row[h] * 64 + ((l_c[h] ^ ((l_row[h] >> 1) & 3)) << 4));
    }

    #define LD_STAGE(s, kt) do { \
        uint32_t abase_ = sb + (s) * STAGE_BYTES; \
        uint32_t bbase_ = abase_ + 8192; \
        _Pragma("unroll") \
        for (int h = 0; h < 4; h++) { \
            cp16(abase_ + l_sw[h], Ag + (size_t)l_row[h] * Kn + (kt) * 32 + l_c[h] * 8); \
            cp16(bbase_ + l_sw[h], Bg + (size_t)l_row[h] * Kn + (kt) * 32 + l_c[h] * 8); \
        } \
    } while (0)

    LD_STAGE(0, 0); CP_COMMIT();
    LD_STAGE(1, 1); CP_COMMIT();
    LD_STAGE(2, 2); CP_COMMIT();

    float acc[4][8][4];
    #pragma unroll
    for (int i = 0; i < 4; i++)
        #pragma unroll
        for (int j = 0; j < 8; j++)
            #pragma unroll
            for (int q = 0; q < 4; q++) acc[i][j][q] = 0.0f;

    const int a_row_l = lane & 15;
    const int a_csel  = lane >> 4;
    const int b_row_l = ((lane >> 4) << 3) + (lane & 7);
    const int b_csel  = (lane >> 3) & 1;

    int stage = 0;
    for (int kt = 0; kt < KT; kt++) {
        CP_WAIT2();
        __syncthreads();
        if (kt + 3 < KT) {
            int s3 = stage + 3; if (s3 >= NSTAGE) s3 -= NSTAGE;
            LD_STAGE(s3, kt + 3);
        }
        CP_COMMIT();

        const uint32_t abase = sb + stage * STAGE_BYTES;
        const uint32_t bbase = abase + 8192;

        #pragma unroll
        for (int k16 = 0; k16 < 2; k16++) {
            uint32_t ar[4][4], br[4][4];
            #pragma unroll
            for (int i = 0; i < 4; i++) {
                int row = warp_m * 64 + i * 16 + a_row_l;
                int c = k16 * 2 + a_csel;
                LDSM4(ar[i], abase + row * 64 + ((c ^ ((row >> 1) & 3)) << 4));
            }
            #pragma unroll
            for (int j = 0; j < 4; j++) {
                int row = warp_n * 64 + j * 16 + b_row_l;
                int c = k16 * 2 + b_csel;
                LDSM4(br[j], bbase + row * 64 + ((c ^ ((row >> 1) & 3)) << 4));
            }
            #pragma unroll
            for (int i = 0; i < 4; i++)
                #pragma unroll
                for (int j = 0; j < 8; j++)
                    MMA16816(acc[i][j], ar[i], br[j >> 1][(j & 1) * 2],
                             br[j >> 1][(j & 1) * 2 + 1]);
        }
        if (++stage == NSTAGE) stage = 0;
    }

    // epilogue
    #pragma unroll
    for (int i = 0; i < 4; i++) {
        const int r0 = m0 + warp_m * 64 + i * 16 + (lane >> 2);
        #pragma unroll
        for (int j = 0; j < 8; j++) {
            const int col = n0 + warp_n * 64 + j * 8 + (lane & 3) * 2;
            float2 v0 = make_float2(acc[i][j][0], acc[i][j][1]);
            float2 v1 = make_float2(acc[i][j][2], acc[i][j][3]);
            if (BIAS) {
                float b0v = bias[col], b1v = bias[col + 1];
                v0.x += b0v; v0.y += b1v; v1.x += b0v; v1.y += b1v;
            }
            *reinterpret_cast<float2*>(&C[(size_t)r0 * Nn + col]) = v0;
            *reinterpret_cast<float2*>(&C[(size_t)(r0 + 8) * Nn + col]) = v1;
        }
    }
}

// ======================= conversion kernels =======================
__global__ void f2h_k(const float4* __restrict__ in, __half2* __restrict__ out, int n4) {
    int i = blockIdx.x * blockDim.x + threadIdx.x;
    if (i < n4) {
        float4 v = in[i];
        out[2 * i]     = __floats2half2_rn(v.x, v.y);
        out[2 * i + 1] = __floats2half2_rn(v.z, v.w);
    }
}

// in [R, Cc] f32 row-major -> out [Cc, R] fp16 row-major
__global__ void transpose_h_k(const float* __restrict__ in, __half* __restrict__ out,
                              int R, int Cc) {
    __shared__ float t[32][33];
    const int bx = blockIdx.x * 32;
    const int by = blockIdx.y * 32;
    const int tx = threadIdx.x, ty = threadIdx.y;
#pragma unroll
    for (int j = 0; j < 32; j += 8)
        t[ty + j][tx] = in[(size_t)(by + ty + j) * Cc + bx + tx];
    __syncthreads();
#pragma unroll
    for (int j = 0; j < 32; j += 8)
        out[(size_t)(bx + ty + j) * R + by + tx] = __float2half_rn(t[tx][ty + j]);
}

// ======================= per-batch attention kernel =======================
__global__ void __launch_bounds__(512) attn_kernel(
    const float* __restrict__ qkv,
    const float* __restrict__ W_E, const float* __restrict__ W_F,
    __half* __restrict__ ho, float* __restrict__ sel_out)
{
    __shared__ float s[SEQ * QKVC];  // 48 KB
    const int b = blockIdx.x;
    const int tid = threadIdx.x;

    const float4* src = reinterpret_cast<const float4*>(qkv + (size_t)b * SEQ * QKVC);
    float4* dst = reinterpret_cast<float4*>(s);
#pragma unroll
    for (int i = 0; i < 6; i++) dst[tid + i * 512] = src[tid + i * 512];
    __syncthreads();

    const int h = tid >> 5, lane = tid & 31;
    const int d0 = lane << 1;

    float q[SEQ][2], kk[SEQ][2], vv[SEQ][2];
#pragma unroll
    for (int n = 0; n < SEQ; n++) {
#pragma unroll
        for (int j = 0; j < 2; j++) {
            q[n][j]  = s[n * QKVC +            h * HDIM + d0 + j] * 0.125f;
            kk[n][j] = s[n * QKVC + CDIM +     h * HDIM + d0 + j];
            vv[n][j] = s[n * QKVC + 2 * CDIM + h * HDIM + d0 + j];
        }
    }

    float wE[16], wF[16];
#pragma unroll
    for (int i = 0; i < 16; i++) { wE[i] = __ldg(&W_E[i]); wF[i] = __ldg(&W_F[i]); }

    float klow[PDIM][2], vlow[PDIM][2];
#pragma unroll
    for (int p = 0; p < PDIM; p++)
#pragma unroll
        for (int j = 0; j < 2; j++) {
            klow[p][j] = wE[p*4+0]*kk[0][j] + wE[p*4+1]*kk[1][j]
                       + wE[p*4+2]*kk[2][j] + wE[p*4+3]*kk[3][j];
            vlow[p][j] = wF[p*4+0]*vv[0][j] + wF[p*4+1]*vv[1][j]
                       + wF[p*4+2]*vv[2][j] + wF[p*4+3]*vv[3][j];
        }

    float attn[SEQ][PDIM];
#pragma unroll
    for (int n = 0; n < SEQ; n++)
#pragma unroll
        for (int p = 0; p < PDIM; p++) {
            float part = q[n][0]*klow[p][0] + q[n][1]*klow[p][1];
#pragma unroll
            for (int o = 16; o > 0; o >>= 1)
                part += __shfl_xor_sync(0xffffffffu, part, o);
            attn[n][p] = part;
        }

#pragma unroll
    for (int n = 0; n < SEQ; n++) {
        float mx = fmaxf(fmaxf(attn[n][0], attn[n][1]), fmaxf(attn[n][2], attn[n][3]));
        float e0 = expf(attn[n][0]-mx), e1 = expf(attn[n][1]-mx);
        float e2 = expf(attn[n][2]-mx), e3 = expf(attn[n][3]-mx);
        float inv = 1.0f / (e0 + e1 + e2 + e3);
        attn[n][0] = e0*inv; attn[n][1] = e1*inv; attn[n][2] = e2*inv; attn[n][3] = e3*inv;
    }

#pragma unroll
    for (int n = 0; n < SEQ; n++) {
        float o0 = attn[n][0]*vlow[0][0] + attn[n][1]*vlow[1][0]
                 + attn[n][2]*vlow[2][0] + attn[n][3]*vlow[3][0];
        float o1 = attn[n][0]*vlow[0][1] + attn[n][1]*vlow[1][1]
                 + attn[n][2]*vlow[2][1] + attn[n][3]*vlow[3][1];
        *reinterpret_cast<__half2*>(
            &ho[(size_t)(b * SEQ + n) * CDIM + h * HDIM + d0]) =
            __floats2half2_rn(o0, o1);
    }

    float selval = 0.0f;
#pragma unroll
    for (int g = 0; g < HEADS; g++) {
        float part = q[1][0] * s[2*QKVC + CDIM + g*HDIM + d0]
                   + q[1][1] * s[2*QKVC + CDIM + g*HDIM + d0 + 1];
#pragma unroll
        for (int o = 16; o > 0; o >>= 1)
            part += __shfl_xor_sync(0xffffffffu, part, o);
        if (lane == g) selval = part;
    }
    if (lane < HEADS)
        sel_out[(size_t)b * HEADS * HEADS + h * HEADS + lane] =
            1.0f / (1.0f + expf(-selval));
}

// ======================= launch =======================
extern "C" void kernel_launch(void* const* d_in, const int* in_sizes, int n_in,
                              void* d_out, int out_size) {
    const float* x      = (const float*)d_in[0];
    const float* W_qkv  = (const float*)d_in[1];
    const float* W_proj = (const float*)d_in[2];
    const float* b_proj = (const float*)d_in[3];
    const float* W_E    = (const float*)d_in[4];
    const float* W_F    = (const float*)d_in[5];
    float* out = (float*)d_out;
    float* sel = out + OUT_ELEMS;

    static __half *xh = nullptr, *wqh = nullptr, *wph = nullptr, *hoh = nullptr;
    static float *qkv = nullptr;
    if (!xh) {
        cudaGetSymbolAddress((void**)&xh,  g_xh);
        cudaGetSymbolAddress((void**)&wqh, g_wqh);
        cudaGetSymbolAddress((void**)&wph, g_wph);
        cudaGetSymbolAddress((void**)&hoh, g_hoh);
        cudaGetSymbolAddress((void**)&qkv, g_qkv);
        cudaFuncSetAttribute(gemm_hmma<false>,
            cudaFuncAttributeMaxDynamicSharedMemorySize, G_SMEM);
        cudaFuncSetAttribute(gemm_hmma<true>,
            cudaFuncAttributeMaxDynamicSharedMemorySize, G_SMEM);
    }

    // conversions
    f2h_k<<<(OUT_ELEMS / 4 + 255) / 256, 256>>>(
        (const float4*)x, (__half2*)xh, (int)(OUT_ELEMS / 4));
    transpose_h_k<<<dim3(QKVC / 32, CDIM / 32), dim3(32, 8)>>>(
        W_qkv, wqh, CDIM, QKVC);
    f2h_k<<<(CDIM * CDIM / 4 + 255) / 256, 256>>>(
        (const float4*)W_proj, (__half2*)wph, CDIM * CDIM / 4);

    // 1) qkv = x @ W_qkv
    gemm_hmma<false><<<dim3(QKVC / 128, MROWS / 128), 128, G_SMEM>>>(
        xh, wqh, nullptr, qkv, MROWS, QKVC, CDIM);
    // 2) attention middle + sel gate (fp32 math, fp16 output for GEMM2)
    attn_kernel<<<BATCH, 512>>>(qkv, W_E, W_F, hoh, sel);
    // 3) out = ho @ W_proj^T + b_proj
    gemm_hmma<true><<<dim3(CDIM / 128, MROWS / 128), 128, G_SMEM>>>(
        hoh, wph, b_proj, out, MROWS, CDIM, CDIM);
}